// round 16
// baseline (speedup 1.0000x reference)
#include <cuda_runtime.h>
#include <cuda_fp16.h>
#include <math.h>
#include <stdint.h>

#define D_MODEL   1024
#define HIDDEN    4096
#define N_EXPERTS 8
#define T_TOKENS  16384
#define MAX_ROWS  (T_TOKENS * 2)

// CTA 128x64, 4 warps (2M x 2N), warp 64x32, fp16-in fp32-acc m16n8k16
#define TILE_M 128
#define TILE_N 64
#define TBK    32                 // K halfs per stage (64 B per row)
#define ROWH   80                 // padded row stride in bytes
#define ABUF   (128 * ROWH)       // 10240 B (A per stage)
#define BBUF   (64 * ROWH)        // 5120 B (B per stage)
#define STAGEB (ABUF + BBUF)      // 15360 B
#define NSTAGE 3
#define SMEM_TOTAL (NSTAGE * STAGEB)   // 46080 B -> 4 CTAs/SM (regs permitting)

// ---------------- scratch ----------------
__device__ int    g_count[N_EXPERTS];
__device__ int    g_tok[N_EXPERTS * T_TOKENS];
__device__ float  g_wt [N_EXPERTS * T_TOKENS];
__device__ __half g_hh [(size_t)MAX_ROWS * HIDDEN];
__device__ __half g_xh [(size_t)T_TOKENS * D_MODEL];
__device__ __half g_w1h[(size_t)N_EXPERTS * HIDDEN * D_MODEL]; // [E][N=4096][K=1024]
__device__ __half g_w2h[(size_t)N_EXPERTS * D_MODEL * HIDDEN]; // [E][N=1024][K=4096]

// ---------------- helpers ----------------
__device__ __forceinline__ uint32_t smem_u32(const void* p) {
    uint32_t a;
    asm("{ .reg .u64 t; cvta.to.shared.u64 t, %1; cvt.u32.u64 %0, t; }" : "=r"(a) : "l"(p));
    return a;
}
#define CP_ASYNC16(dst, src) \
    asm volatile("cp.async.cg.shared.global [%0], [%1], 16;" :: "r"(dst), "l"(src))
#define CP_COMMIT() asm volatile("cp.async.commit_group;" ::: "memory")
#define CP_WAIT1()  asm volatile("cp.async.wait_group 1;" ::: "memory")
#define CP_WAIT0()  asm volatile("cp.async.wait_group 0;" ::: "memory")

#define LDSM_X4(r0, r1, r2, r3, addr) \
    asm volatile("ldmatrix.sync.aligned.m8n8.x4.shared.b16 {%0,%1,%2,%3}, [%4];" \
        : "=r"(r0), "=r"(r1), "=r"(r2), "=r"(r3) : "r"(addr))

__device__ __forceinline__ void mma_f16(float* d, const uint32_t* a, const uint32_t* b) {
    asm volatile(
        "mma.sync.aligned.m16n8k16.row.col.f32.f16.f16.f32 "
        "{%0,%1,%2,%3}, {%4,%5,%6,%7}, {%8,%9}, {%0,%1,%2,%3};"
        : "+f"(d[0]), "+f"(d[1]), "+f"(d[2]), "+f"(d[3])
        : "r"(a[0]), "r"(a[1]), "r"(a[2]), "r"(a[3]), "r"(b[0]), "r"(b[1]));
}
#define RED_ADD_V2(ptr, v0, v1) \
    asm volatile("red.global.add.v2.f32 [%0], {%1, %2};" :: "l"(ptr), "f"(v0), "f"(v1) : "memory")

// ---------------- zero routing counters ----------------
__global__ void zero_counts_kernel() {
    if (threadIdx.x < N_EXPERTS) g_count[threadIdx.x] = 0;
}

// ---------------- transpose weights -> fp16 (side stream) ----------------
__global__ void transpose_w_kernel(const float* __restrict__ w1, const float* __restrict__ w2) {
    __shared__ float tile[32][33];
    const int z = blockIdx.z;
    const float* src; __half* dst; int R, C;
    if (z < N_EXPERTS) {
        src = w1 + (size_t)z * D_MODEL * HIDDEN; dst = g_w1h + (size_t)z * HIDDEN * D_MODEL;
        R = D_MODEL; C = HIDDEN;
    } else {
        src = w2 + (size_t)(z - N_EXPERTS) * HIDDEN * D_MODEL;
        dst = g_w2h + (size_t)(z - N_EXPERTS) * D_MODEL * HIDDEN;
        R = HIDDEN; C = D_MODEL;
    }
    const int c0 = blockIdx.x * 32, r0 = blockIdx.y * 32;
    if (c0 >= C || r0 >= R) return;
    const int tx = threadIdx.x, ty = threadIdx.y;
#pragma unroll
    for (int j = 0; j < 32; j += 8)
        tile[ty + j][tx] = src[(size_t)(r0 + ty + j) * C + c0 + tx];
    __syncthreads();
#pragma unroll
    for (int j = 0; j < 32; j += 8)
        dst[(size_t)(c0 + ty + j) * R + r0 + tx] = __float2half_rn(tile[tx][ty + j]);
}

// ---------------- gating (+ fp16 cast of x + out zeroing) ----------------
__global__ void gate_kernel(const float* __restrict__ x, const float* __restrict__ gw,
                            float* __restrict__ out) {
    int gtid = blockIdx.x * blockDim.x + threadIdx.x;
    int warp = gtid >> 5;
    int lane = gtid & 31;
    if (warp >= T_TOKENS) return;

    {
        float4* orow = (float4*)(out + (size_t)warp * D_MODEL);
#pragma unroll
        for (int j = 0; j < D_MODEL / 4 / 32; j++)
            orow[lane + j * 32] = make_float4(0.f, 0.f, 0.f, 0.f);
    }

    const float* xr = x + (size_t)warp * D_MODEL;
    __half* xo = g_xh + (size_t)warp * D_MODEL;
    float acc[N_EXPERTS];
#pragma unroll
    for (int e = 0; e < N_EXPERTS; e++) acc[e] = 0.f;
    for (int d = lane; d < D_MODEL; d += 32) {
        float xv = xr[d];
        xo[d] = __float2half_rn(xv);
        float4 g0 = *(const float4*)(gw + d * N_EXPERTS);
        float4 g1 = *(const float4*)(gw + d * N_EXPERTS + 4);
        acc[0] += xv * g0.x; acc[1] += xv * g0.y; acc[2] += xv * g0.z; acc[3] += xv * g0.w;
        acc[4] += xv * g1.x; acc[5] += xv * g1.y; acc[6] += xv * g1.z; acc[7] += xv * g1.w;
    }
#pragma unroll
    for (int off = 16; off > 0; off >>= 1)
#pragma unroll
        for (int e = 0; e < N_EXPERTS; e++)
            acc[e] += __shfl_xor_sync(0xffffffffu, acc[e], off);

    if (lane == 0) {
        int i0 = 0; float m0 = acc[0];
#pragma unroll
        for (int e = 1; e < N_EXPERTS; e++) if (acc[e] > m0) { m0 = acc[e]; i0 = e; }
        int i1 = -1; float m1 = -1e30f;
#pragma unroll
        for (int e = 0; e < N_EXPERTS; e++) if (e != i0 && acc[e] > m1) { m1 = acc[e]; i1 = e; }
        float ex = expf(m1 - m0);
        float w0 = 1.0f / (1.0f + ex);
        float w1v = ex / (1.0f + ex);
        int p0 = atomicAdd(&g_count[i0], 1);
        g_tok[i0 * T_TOKENS + p0] = warp; g_wt[i0 * T_TOKENS + p0] = w0;
        int p1 = atomicAdd(&g_count[i1], 1);
        g_tok[i1 * T_TOKENS + p1] = warp; g_wt[i1 * T_TOKENS + p1] = w1v;
    }
}

// ============================================================================
// fp32-acc GEMM core: r5 per-warp instruction stream, but CTA = 4 warps only
// (4 independent CTAs/SM -> smaller barriers, more overlapped pipelines).
// ============================================================================
struct GemmCtx {
    const __half* a;   // A row base (row = tid)
    const __half* b;   // B row base + chunk (row = tid>>1, chunk = tid&1)
    uint32_t dA, dB;
};

__device__ __forceinline__ void gemm_issue(const GemmCtx& ctx, int kt, uint32_t soff) {
    const __half* a = ctx.a + kt * TBK;
    const __half* b = ctx.b + kt * TBK;
#pragma unroll
    for (int j = 0; j < 4; j++)
        CP_ASYNC16(ctx.dA + soff + j * 16, a + j * 8);
#pragma unroll
    for (int j = 0; j < 2; j++)
        CP_ASYNC16(ctx.dB + soff + j * 16, b + j * 8);
    CP_COMMIT();
}

__device__ __forceinline__ void gemm_mainloop(
    uint32_t sb, const GemmCtx& ctx, int NT,
    float acc[4][4][4], int wid, int lane)
{
    const int warpM = wid & 1, warpN = wid >> 1;   // 2M x 2N
    const uint32_t rowA = (lane & 7) + ((lane >> 3) & 1) * 8;
    const uint32_t colA = ((uint32_t)lane >> 4) * 16;
    const uint32_t rowB = (lane & 7) + (((uint32_t)lane >> 4) & 1) * 8;
    const uint32_t colB = (((uint32_t)lane >> 3) & 1) * 16;
    const uint32_t aoff = sb +        (warpM * 64 + rowA) * ROWH + colA;
    const uint32_t boff = sb + ABUF + (warpN * 32 + rowB) * ROWH + colB;

    gemm_issue(ctx, 0, 0);
    gemm_issue(ctx, 1, STAGEB);

    for (int kt = 0; kt < NT; kt++) {
        if (kt <= NT - 2) CP_WAIT1(); else CP_WAIT0();
        __syncthreads();
        if (kt + 2 < NT) gemm_issue(ctx, kt + 2, (uint32_t)((kt + 2) % NSTAGE) * STAGEB);

        const uint32_t so = (uint32_t)(kt % NSTAGE) * STAGEB;
        const uint32_t ab = aoff + so, bb = boff + so;
#pragma unroll
        for (int ks = 0; ks < 2; ks++) {
            uint32_t a[4][4], b[4][2];
#pragma unroll
            for (int mi = 0; mi < 4; mi++)
                LDSM_X4(a[mi][0], a[mi][1], a[mi][2], a[mi][3],
                        ab + (uint32_t)mi * 16 * ROWH + ks * 32);
            LDSM_X4(b[0][0], b[0][1], b[1][0], b[1][1], bb + ks * 32);
            LDSM_X4(b[2][0], b[2][1], b[3][0], b[3][1], bb + 16 * ROWH + ks * 32);
#pragma unroll
            for (int mi = 0; mi < 4; mi++)
#pragma unroll
                for (int ni = 0; ni < 4; ni++)
                    mma_f16(acc[mi][ni], a[mi], b[ni]);
        }
    }
}

// ---------------- GEMM1 + SiLU -> g_hh (per-expert) ----------------
__global__ void __launch_bounds__(128, 4)
gemm1_mma(int e) {
    const int mcnt  = g_count[e];
    const int mbase = blockIdx.y * TILE_M;
    if (mbase >= mcnt) return;
    const int nbase = blockIdx.x * TILE_N;

    int hoff = 0;
    for (int i = 0; i < e; i++) hoff += g_count[i];

    extern __shared__ char smem_raw[];
    const uint32_t sb = smem_u32(smem_raw);
    const int tid = threadIdx.x, wid = tid >> 5, lane = tid & 31;

    GemmCtx ctx;
    {
        // A: 128 threads, one row each (4 chunks of 16B per stage)
        int gm = mbase + tid; if (gm >= mcnt) gm = mcnt - 1;
        ctx.a  = g_xh + (size_t)g_tok[e * T_TOKENS + gm] * D_MODEL;
        ctx.dA = sb + tid * ROWH;
        // B: 64 rows x 2 threads (2 chunks of 16B per stage each)
        const int rb2 = tid >> 1, sb2 = tid & 1;
        ctx.b  = g_w1h + (size_t)e * HIDDEN * D_MODEL + (size_t)(nbase + rb2) * D_MODEL + sb2 * 16;
        ctx.dB = sb + ABUF + rb2 * ROWH + sb2 * 32;
    }

    float acc[4][4][4];
#pragma unroll
    for (int mi = 0; mi < 4; mi++)
#pragma unroll
        for (int ni = 0; ni < 4; ni++)
#pragma unroll
            for (int k = 0; k < 4; k++) acc[mi][ni][k] = 0.f;

    gemm_mainloop(sb, ctx, D_MODEL / TBK, acc, wid, lane);

    const int warpM = wid & 1, warpN = wid >> 1;
    const int rb = mbase + warpM * 64 + (lane >> 2);
    const int cb = nbase + warpN * 32 + (lane & 3) * 2;
#pragma unroll
    for (int mi = 0; mi < 4; mi++) {
#pragma unroll
        for (int half = 0; half < 2; half++) {
            const int gm = rb + mi * 16 + half * 8;
            if (gm < mcnt) {
                __half* hp = g_hh + (size_t)(hoff + gm) * HIDDEN + cb;
#pragma unroll
                for (int ni = 0; ni < 4; ni++) {
                    float v0 = acc[mi][ni][half * 2];
                    float v1 = acc[mi][ni][half * 2 + 1];
                    v0 = v0 / (1.0f + __expf(-v0));
                    v1 = v1 / (1.0f + __expf(-v1));
                    *(__half2*)(hp + ni * 8) = __floats2half2_rn(v0, v1);
                }
            }
        }
    }
}

// ---------------- GEMM2 + weighted scatter (per-expert) ----------------
__global__ void __launch_bounds__(128, 4)
gemm2_mma(int e, float* __restrict__ out) {
    const int mcnt  = g_count[e];
    const int mbase = blockIdx.y * TILE_M;
    if (mbase >= mcnt) return;
    const int nbase = blockIdx.x * TILE_N;

    int hoff = 0;
    for (int i = 0; i < e; i++) hoff += g_count[i];

    extern __shared__ char smem_raw[];
    const uint32_t sb = smem_u32(smem_raw);
    const int tid = threadIdx.x, wid = tid >> 5, lane = tid & 31;

    GemmCtx ctx;
    {
        int gm = mbase + tid; if (gm >= mcnt) gm = mcnt - 1;
        ctx.a  = g_hh + (size_t)(hoff + gm) * HIDDEN;
        ctx.dA = sb + tid * ROWH;
        const int rb2 = tid >> 1, sb2 = tid & 1;
        ctx.b  = g_w2h + (size_t)e * D_MODEL * HIDDEN + (size_t)(nbase + rb2) * HIDDEN + sb2 * 16;
        ctx.dB = sb + ABUF + rb2 * ROWH + sb2 * 32;
    }

    float acc[4][4][4];
#pragma unroll
    for (int mi = 0; mi < 4; mi++)
#pragma unroll
        for (int ni = 0; ni < 4; ni++)
#pragma unroll
            for (int k = 0; k < 4; k++) acc[mi][ni][k] = 0.f;

    gemm_mainloop(sb, ctx, HIDDEN / TBK, acc, wid, lane);

    const int warpM = wid & 1, warpN = wid >> 1;
    const int rb = mbase + warpM * 64 + (lane >> 2);
    const int cb = nbase + warpN * 32 + (lane & 3) * 2;
    const int* tks = g_tok + e * T_TOKENS;
    const float* wts = g_wt + e * T_TOKENS;
#pragma unroll
    for (int mi = 0; mi < 4; mi++) {
#pragma unroll
        for (int half = 0; half < 2; half++) {
            const int gm = rb + mi * 16 + half * 8;
            if (gm < mcnt) {
                const int tok = tks[gm];
                const float w = wts[gm];
                float* op = out + (size_t)tok * D_MODEL + cb;
#pragma unroll
                for (int ni = 0; ni < 4; ni++)
                    RED_ADD_V2(op + ni * 8, w * acc[mi][ni][half * 2],
                                            w * acc[mi][ni][half * 2 + 1]);
            }
        }
    }
}

// ---------------- launch: two-chain expert pipelining (ONE extra stream) ----------------
extern "C" void kernel_launch(void* const* d_in, const int* in_sizes, int n_in,
                              void* d_out, int out_size) {
    const float* x  = (const float*)d_in[0];
    const float* gw = (const float*)d_in[1];
    const float* w1 = (const float*)d_in[2];
    const float* w2 = (const float*)d_in[3];
    float* out = (float*)d_out;

    static cudaStream_t side = nullptr;
    static cudaEvent_t ev_fork = nullptr, ev_side = nullptr, ev_ready = nullptr, ev_done = nullptr;
    static bool init_done = false;
    if (!init_done) {
        cudaFuncSetAttribute(gemm1_mma, cudaFuncAttributeMaxDynamicSharedMemorySize, SMEM_TOTAL);
        cudaFuncSetAttribute(gemm2_mma, cudaFuncAttributeMaxDynamicSharedMemorySize, SMEM_TOTAL);
        cudaStreamCreateWithFlags(&side, cudaStreamNonBlocking);
        cudaEventCreateWithFlags(&ev_fork,  cudaEventDisableTiming);
        cudaEventCreateWithFlags(&ev_side,  cudaEventDisableTiming);
        cudaEventCreateWithFlags(&ev_ready, cudaEventDisableTiming);
        cudaEventCreateWithFlags(&ev_done,  cudaEventDisableTiming);
        init_done = true;
    }

    zero_counts_kernel<<<1, 32>>>();
    cudaEventRecord(ev_fork, 0);
    cudaStreamWaitEvent(side, ev_fork, 0);
    {
        dim3 g(HIDDEN / 32, HIDDEN / 32, 2 * N_EXPERTS);
        transpose_w_kernel<<<g, dim3(32, 8), 0, side>>>(w1, w2);
    }
    cudaEventRecord(ev_side, side);

    gate_kernel<<<T_TOKENS / 8, 256>>>(x, gw, out);
    cudaStreamWaitEvent(0, ev_side, 0);
    cudaEventRecord(ev_ready, 0);
    cudaStreamWaitEvent(side, ev_ready, 0);

    dim3 g1(HIDDEN / TILE_N, T_TOKENS / TILE_M, 1);   // (64, 128)
    dim3 g2(D_MODEL / TILE_N, T_TOKENS / TILE_M, 1);  // (16, 128)
    for (int e = 0; e < N_EXPERTS; e += 2) {
        gemm1_mma<<<g1, 128, SMEM_TOTAL, 0>>>(e);
        gemm2_mma<<<g2, 128, SMEM_TOTAL, 0>>>(e, out);
        gemm1_mma<<<g1, 128, SMEM_TOTAL, side>>>(e + 1);
        gemm2_mma<<<g2, 128, SMEM_TOTAL, side>>>(e + 1, out);
    }
    cudaEventRecord(ev_done, side);
    cudaStreamWaitEvent(0, ev_done, 0);
}

// round 17
// speedup vs baseline: 1.4843x; 1.4843x over previous
#include <cuda_runtime.h>
#include <cuda_fp16.h>
#include <math.h>
#include <stdint.h>

#define D_MODEL   1024
#define HIDDEN    4096
#define N_EXPERTS 8
#define T_TOKENS  16384
#define MAX_ROWS  (T_TOKENS * 2)

// tile config (fp16 in, fp32 acc, m16n8k16): CTA 128x128, 8 warps, warp 64x32
#define TILE_M 128
#define TILE_N 128
#define TBK    32                 // K halfs per stage (64 B per row)
#define ROWH   80                 // padded row stride in bytes (40 halfs)
#define MBUF   (128 * ROWH)       // 10240 B per matrix per stage
#define STAGEB (2 * MBUF)         // 20480 B per stage
#define NSTAGE 3
#define SMEM_TOTAL (NSTAGE * STAGEB)   // 61440 B -> 2 CTAs/SM

// ---------------- scratch (static device globals; no allocs) ----------------
__device__ int    g_count[N_EXPERTS];
__device__ int    g_tok[N_EXPERTS * T_TOKENS];
__device__ float  g_wt [N_EXPERTS * T_TOKENS];
__device__ __half g_hh [(size_t)MAX_ROWS * HIDDEN];            // compact fp16 h
__device__ __half g_xh [(size_t)T_TOKENS * D_MODEL];
__device__ __half g_w1h[(size_t)N_EXPERTS * HIDDEN * D_MODEL]; // [E][N=4096][K=1024]
__device__ __half g_w2h[(size_t)N_EXPERTS * D_MODEL * HIDDEN]; // [E][N=1024][K=4096]

// ---------------- helpers ----------------
__device__ __forceinline__ uint32_t smem_u32(const void* p) {
    uint32_t a;
    asm("{ .reg .u64 t; cvta.to.shared.u64 t, %1; cvt.u32.u64 %0, t; }" : "=r"(a) : "l"(p));
    return a;
}
#define CP_ASYNC16(dst, src) \
    asm volatile("cp.async.cg.shared.global [%0], [%1], 16;" :: "r"(dst), "l"(src))
#define CP_COMMIT() asm volatile("cp.async.commit_group;" ::: "memory")
#define CP_WAIT1()  asm volatile("cp.async.wait_group 1;" ::: "memory")
#define CP_WAIT0()  asm volatile("cp.async.wait_group 0;" ::: "memory")

#define LDSM_X4(r0, r1, r2, r3, addr) \
    asm volatile("ldmatrix.sync.aligned.m8n8.x4.shared.b16 {%0,%1,%2,%3}, [%4];" \
        : "=r"(r0), "=r"(r1), "=r"(r2), "=r"(r3) : "r"(addr))

__device__ __forceinline__ void mma_f16(float* d, const uint32_t* a, const uint32_t* b) {
    asm volatile(
        "mma.sync.aligned.m16n8k16.row.col.f32.f16.f16.f32 "
        "{%0,%1,%2,%3}, {%4,%5,%6,%7}, {%8,%9}, {%0,%1,%2,%3};"
        : "+f"(d[0]), "+f"(d[1]), "+f"(d[2]), "+f"(d[3])
        : "r"(a[0]), "r"(a[1]), "r"(a[2]), "r"(a[3]), "r"(b[0]), "r"(b[1]));
}
#define RED_ADD_V2(ptr, v0, v1) \
    asm volatile("red.global.add.v2.f32 [%0], {%1, %2};" :: "l"(ptr), "f"(v0), "f"(v1) : "memory")

// ---------------- zero routing counters ----------------
__global__ void zero_counts_kernel() {
    if (threadIdx.x < N_EXPERTS) g_count[threadIdx.x] = 0;
}

// ---------------- transpose w1 -> fp16 (needed before gemm1) ----------------
__global__ void transpose_w1_kernel(const float* __restrict__ w1) {
    __shared__ float tile[32][33];
    const int z = blockIdx.z;                       // expert
    const float* src = w1 + (size_t)z * D_MODEL * HIDDEN;   // [1024 x 4096]
    __half* dst = g_w1h + (size_t)z * HIDDEN * D_MODEL;     // [4096 x 1024]
    const int c0 = blockIdx.x * 32, r0 = blockIdx.y * 32;   // c<4096, r<1024
    const int tx = threadIdx.x, ty = threadIdx.y;
#pragma unroll
    for (int j = 0; j < 32; j += 8)
        tile[ty + j][tx] = src[(size_t)(r0 + ty + j) * HIDDEN + c0 + tx];
    __syncthreads();
#pragma unroll
    for (int j = 0; j < 32; j += 8)
        dst[(size_t)(c0 + ty + j) * D_MODEL + r0 + tx] = __float2half_rn(tile[tx][ty + j]);
}

// ---------------- transpose w2 -> fp16 (needed before gemm2; overlaps gemm1) ----------------
__global__ void transpose_w2_kernel(const float* __restrict__ w2) {
    __shared__ float tile[32][33];
    const int z = blockIdx.z;
    const float* src = w2 + (size_t)z * HIDDEN * D_MODEL;   // [4096 x 1024]
    __half* dst = g_w2h + (size_t)z * D_MODEL * HIDDEN;     // [1024 x 4096]
    const int c0 = blockIdx.x * 32, r0 = blockIdx.y * 32;   // c<1024, r<4096
    const int tx = threadIdx.x, ty = threadIdx.y;
#pragma unroll
    for (int j = 0; j < 32; j += 8)
        tile[ty + j][tx] = src[(size_t)(r0 + ty + j) * D_MODEL + c0 + tx];
    __syncthreads();
#pragma unroll
    for (int j = 0; j < 32; j += 8)
        dst[(size_t)(c0 + ty + j) * HIDDEN + r0 + tx] = __float2half_rn(tile[tx][ty + j]);
}

// ---------------- gating (+ fp16 cast of x + out zeroing) ----------------
__global__ void gate_kernel(const float* __restrict__ x, const float* __restrict__ gw,
                            float* __restrict__ out) {
    int gtid = blockIdx.x * blockDim.x + threadIdx.x;
    int warp = gtid >> 5;
    int lane = gtid & 31;
    if (warp >= T_TOKENS) return;

    {
        float4* orow = (float4*)(out + (size_t)warp * D_MODEL);
#pragma unroll
        for (int j = 0; j < D_MODEL / 4 / 32; j++)
            orow[lane + j * 32] = make_float4(0.f, 0.f, 0.f, 0.f);
    }

    const float* xr = x + (size_t)warp * D_MODEL;
    __half* xo = g_xh + (size_t)warp * D_MODEL;
    float acc[N_EXPERTS];
#pragma unroll
    for (int e = 0; e < N_EXPERTS; e++) acc[e] = 0.f;
    for (int d = lane; d < D_MODEL; d += 32) {
        float xv = xr[d];
        xo[d] = __float2half_rn(xv);
        float4 g0 = *(const float4*)(gw + d * N_EXPERTS);
        float4 g1 = *(const float4*)(gw + d * N_EXPERTS + 4);
        acc[0] += xv * g0.x; acc[1] += xv * g0.y; acc[2] += xv * g0.z; acc[3] += xv * g0.w;
        acc[4] += xv * g1.x; acc[5] += xv * g1.y; acc[6] += xv * g1.z; acc[7] += xv * g1.w;
    }
#pragma unroll
    for (int off = 16; off > 0; off >>= 1)
#pragma unroll
        for (int e = 0; e < N_EXPERTS; e++)
            acc[e] += __shfl_xor_sync(0xffffffffu, acc[e], off);

    if (lane == 0) {
        int i0 = 0; float m0 = acc[0];
#pragma unroll
        for (int e = 1; e < N_EXPERTS; e++) if (acc[e] > m0) { m0 = acc[e]; i0 = e; }
        int i1 = -1; float m1 = -1e30f;
#pragma unroll
        for (int e = 0; e < N_EXPERTS; e++) if (e != i0 && acc[e] > m1) { m1 = acc[e]; i1 = e; }
        float ex = expf(m1 - m0);
        float w0 = 1.0f / (1.0f + ex);
        float w1v = ex / (1.0f + ex);
        int p0 = atomicAdd(&g_count[i0], 1);
        g_tok[i0 * T_TOKENS + p0] = warp; g_wt[i0 * T_TOKENS + p0] = w0;
        int p1 = atomicAdd(&g_count[i1], 1);
        g_tok[i1 * T_TOKENS + p1] = warp; g_wt[i1 * T_TOKENS + p1] = w1v;
    }
}

// ============================================================================
// fp32-acc fp16 mma GEMM core — EXACT r5 configuration (best measured).
// ============================================================================
struct GemmCtx {
    const __half* a;
    const __half* b;
    uint32_t dA, dB;
};

__device__ __forceinline__ void gemm_issue(const GemmCtx& ctx, int kt, uint32_t soff) {
    const __half* a = ctx.a + kt * TBK;
    const __half* b = ctx.b + kt * TBK;
    CP_ASYNC16(ctx.dA + soff,      a);
    CP_ASYNC16(ctx.dA + soff + 16, a + 8);
    CP_ASYNC16(ctx.dB + soff,      b);
    CP_ASYNC16(ctx.dB + soff + 16, b + 8);
    CP_COMMIT();
}

__device__ __forceinline__ void gemm_mainloop(
    uint32_t sb, const GemmCtx& ctx, int NT,
    float acc[4][4][4], int wid, int lane)
{
    const int warpM = wid & 1, warpN = wid >> 1;
    const uint32_t rowA = (lane & 7) + ((lane >> 3) & 1) * 8;
    const uint32_t colA = ((uint32_t)lane >> 4) * 16;
    const uint32_t rowB = (lane & 7) + (((uint32_t)lane >> 4) & 1) * 8;
    const uint32_t colB = (((uint32_t)lane >> 3) & 1) * 16;
    const uint32_t aoff = sb +        (warpM * 64 + rowA) * ROWH + colA;
    const uint32_t boff = sb + MBUF + (warpN * 32 + rowB) * ROWH + colB;

    gemm_issue(ctx, 0, 0);
    gemm_issue(ctx, 1, STAGEB);

    for (int kt = 0; kt < NT; kt++) {
        if (kt <= NT - 2) CP_WAIT1(); else CP_WAIT0();
        __syncthreads();
        if (kt + 2 < NT) gemm_issue(ctx, kt + 2, (uint32_t)((kt + 2) % NSTAGE) * STAGEB);

        const uint32_t so = (uint32_t)(kt % NSTAGE) * STAGEB;
        const uint32_t ab = aoff + so, bb = boff + so;
#pragma unroll
        for (int ks = 0; ks < 2; ks++) {
            uint32_t a[4][4], b[4][2];
#pragma unroll
            for (int mi = 0; mi < 4; mi++)
                LDSM_X4(a[mi][0], a[mi][1], a[mi][2], a[mi][3],
                        ab + (uint32_t)mi * 16 * ROWH + ks * 32);
            LDSM_X4(b[0][0], b[0][1], b[1][0], b[1][1], bb + ks * 32);
            LDSM_X4(b[2][0], b[2][1], b[3][0], b[3][1], bb + 16 * ROWH + ks * 32);
#pragma unroll
            for (int mi = 0; mi < 4; mi++)
#pragma unroll
                for (int ni = 0; ni < 4; ni++)
                    mma_f16(acc[mi][ni], a[mi], b[ni]);
        }
    }
}

// ---------------- GEMM1 + SiLU -> g_hh (per-expert) ----------------
__global__ void __launch_bounds__(256, 2)
gemm1_mma(int e) {
    const int mcnt  = g_count[e];
    const int mbase = blockIdx.y * TILE_M;
    if (mbase >= mcnt) return;
    const int nbase = blockIdx.x * TILE_N;

    int hoff = 0;
    for (int i = 0; i < e; i++) hoff += g_count[i];

    extern __shared__ char smem_raw[];
    const uint32_t sb = smem_u32(smem_raw);
    const int tid = threadIdx.x, wid = tid >> 5, lane = tid & 31;

    GemmCtx ctx;
    {
        const int r = tid >> 1, s = tid & 1;
        int gm = mbase + r; if (gm >= mcnt) gm = mcnt - 1;
        ctx.a  = g_xh + (size_t)g_tok[e * T_TOKENS + gm] * D_MODEL + s * 16;
        ctx.b  = g_w1h + (size_t)e * HIDDEN * D_MODEL + (size_t)(nbase + r) * D_MODEL + s * 16;
        ctx.dA = sb + r * ROWH + s * 32;
        ctx.dB = sb + MBUF + r * ROWH + s * 32;
    }

    float acc[4][4][4];
#pragma unroll
    for (int mi = 0; mi < 4; mi++)
#pragma unroll
        for (int ni = 0; ni < 4; ni++)
#pragma unroll
            for (int k = 0; k < 4; k++) acc[mi][ni][k] = 0.f;

    gemm_mainloop(sb, ctx, D_MODEL / TBK, acc, wid, lane);

    const int warpM = wid & 1, warpN = wid >> 1;
    const int rb = mbase + warpM * 64 + (lane >> 2);
    const int cb = nbase + warpN * 32 + (lane & 3) * 2;
#pragma unroll
    for (int mi = 0; mi < 4; mi++) {
#pragma unroll
        for (int half = 0; half < 2; half++) {
            const int gm = rb + mi * 16 + half * 8;
            if (gm < mcnt) {
                __half* hp = g_hh + (size_t)(hoff + gm) * HIDDEN + cb;
#pragma unroll
                for (int ni = 0; ni < 4; ni++) {
                    float v0 = acc[mi][ni][half * 2];
                    float v1 = acc[mi][ni][half * 2 + 1];
                    v0 = v0 / (1.0f + __expf(-v0));
                    v1 = v1 / (1.0f + __expf(-v1));
                    *(__half2*)(hp + ni * 8) = __floats2half2_rn(v0, v1);
                }
            }
        }
    }
}

// ---------------- GEMM2 + weighted scatter (per-expert) ----------------
__global__ void __launch_bounds__(256, 2)
gemm2_mma(int e, float* __restrict__ out) {
    const int mcnt  = g_count[e];
    const int mbase = blockIdx.y * TILE_M;
    if (mbase >= mcnt) return;
    const int nbase = blockIdx.x * TILE_N;

    int hoff = 0;
    for (int i = 0; i < e; i++) hoff += g_count[i];

    extern __shared__ char smem_raw[];
    const uint32_t sb = smem_u32(smem_raw);
    const int tid = threadIdx.x, wid = tid >> 5, lane = tid & 31;

    GemmCtx ctx;
    {
        const int r = tid >> 1, s = tid & 1;
        int gm = mbase + r; if (gm >= mcnt) gm = mcnt - 1;
        ctx.a  = g_hh + (size_t)(hoff + gm) * HIDDEN + s * 16;
        ctx.b  = g_w2h + (size_t)e * D_MODEL * HIDDEN + (size_t)(nbase + r) * HIDDEN + s * 16;
        ctx.dA = sb + r * ROWH + s * 32;
        ctx.dB = sb + MBUF + r * ROWH + s * 32;
    }

    float acc[4][4][4];
#pragma unroll
    for (int mi = 0; mi < 4; mi++)
#pragma unroll
        for (int ni = 0; ni < 4; ni++)
#pragma unroll
            for (int k = 0; k < 4; k++) acc[mi][ni][k] = 0.f;

    gemm_mainloop(sb, ctx, HIDDEN / TBK, acc, wid, lane);

    const int warpM = wid & 1, warpN = wid >> 1;
    const int rb = mbase + warpM * 64 + (lane >> 2);
    const int cb = nbase + warpN * 32 + (lane & 3) * 2;
    const int* tks = g_tok + e * T_TOKENS;
    const float* wts = g_wt + e * T_TOKENS;
#pragma unroll
    for (int mi = 0; mi < 4; mi++) {
#pragma unroll
        for (int half = 0; half < 2; half++) {
            const int gm = rb + mi * 16 + half * 8;
            if (gm < mcnt) {
                const int tok = tks[gm];
                const float w = wts[gm];
                float* op = out + (size_t)tok * D_MODEL + cb;
#pragma unroll
                for (int ni = 0; ni < 4; ni++)
                    RED_ADD_V2(op + ni * 8, w * acc[mi][ni][half * 2],
                                            w * acc[mi][ni][half * 2 + 1]);
            }
        }
    }
}

// ---------------- launch: split transpose + two-chain expert pipelining ----------------
extern "C" void kernel_launch(void* const* d_in, const int* in_sizes, int n_in,
                              void* d_out, int out_size) {
    const float* x  = (const float*)d_in[0];
    const float* gw = (const float*)d_in[1];
    const float* w1 = (const float*)d_in[2];
    const float* w2 = (const float*)d_in[3];
    float* out = (float*)d_out;

    static cudaStream_t side = nullptr;
    static cudaEvent_t ev_fork = nullptr, ev_t1 = nullptr, ev_t2 = nullptr;
    static cudaEvent_t ev_ready = nullptr, ev_done = nullptr;
    static bool init_done = false;
    if (!init_done) {
        cudaFuncSetAttribute(gemm1_mma, cudaFuncAttributeMaxDynamicSharedMemorySize, SMEM_TOTAL);
        cudaFuncSetAttribute(gemm2_mma, cudaFuncAttributeMaxDynamicSharedMemorySize, SMEM_TOTAL);
        cudaStreamCreateWithFlags(&side, cudaStreamNonBlocking);
        cudaEventCreateWithFlags(&ev_fork,  cudaEventDisableTiming);
        cudaEventCreateWithFlags(&ev_t1,    cudaEventDisableTiming);
        cudaEventCreateWithFlags(&ev_t2,    cudaEventDisableTiming);
        cudaEventCreateWithFlags(&ev_ready, cudaEventDisableTiming);
        cudaEventCreateWithFlags(&ev_done,  cudaEventDisableTiming);
        init_done = true;
    }

    // main: zero counters; fork side
    zero_counts_kernel<<<1, 32>>>();
    cudaEventRecord(ev_fork, 0);
    cudaStreamWaitEvent(side, ev_fork, 0);

    // side: transpose w1 (gates gemm1), then w2 (gates gemm2, overlaps gemm1)
    {
        dim3 gt1(HIDDEN / 32, D_MODEL / 32, N_EXPERTS);   // (128, 32, 8)
        transpose_w1_kernel<<<gt1, dim3(32, 8), 0, side>>>(w1);
        cudaEventRecord(ev_t1, side);
        dim3 gt2(D_MODEL / 32, HIDDEN / 32, N_EXPERTS);   // (32, 128, 8)
        transpose_w2_kernel<<<gt2, dim3(32, 8), 0, side>>>(w2);
        cudaEventRecord(ev_t2, side);
    }

    // main: gate; then wait only for w1 transpose
    gate_kernel<<<T_TOKENS / 8, 256>>>(x, gw, out);
    cudaStreamWaitEvent(0, ev_t1, 0);
    cudaEventRecord(ev_ready, 0);           // gate + w1t complete
    cudaStreamWaitEvent(side, ev_ready, 0); // side (after t2) also sees gate

    dim3 g1(HIDDEN / TILE_N, T_TOKENS / TILE_M, 1);   // (32, 128)
    dim3 g2(D_MODEL / TILE_N, T_TOKENS / TILE_M, 1);  // (8, 128)

    bool main_waited_t2 = false;
    for (int e = 0; e < N_EXPERTS; e += 2) {
        gemm1_mma<<<g1, 256, SMEM_TOTAL, 0>>>(e);
        if (!main_waited_t2) { cudaStreamWaitEvent(0, ev_t2, 0); main_waited_t2 = true; }
        gemm2_mma<<<g2, 256, SMEM_TOTAL, 0>>>(e, out);
        gemm1_mma<<<g1, 256, SMEM_TOTAL, side>>>(e + 1);   // side: already after t2
        gemm2_mma<<<g2, 256, SMEM_TOTAL, side>>>(e + 1, out);
    }
    cudaEventRecord(ev_done, side);
    cudaStreamWaitEvent(0, ev_done, 0);
}